// round 3
// baseline (speedup 1.0000x reference)
#include <cuda_runtime.h>
#include <cuda_bf16.h>
#include <math.h>

#define NN 100000
#define DD 64
#define EE 1000000
#define EPSM 1e-7f

// ---------------- scratch (static __device__, no allocation) ----------------
__device__ int   g_count[NN];
__device__ int   g_incl[NN];
__device__ int   g_bsum[128];
__device__ int   g_boff[128];
__device__ int   g_offset[NN + 1];
__device__ int   g_cursor[NN];
__device__ int   g_ssrc[EE];
__device__ float g_aggout[(size_t)NN * DD];      // 25.6 MB
__device__ float g_h[(size_t)NN * 2 * DD];       // 51.2 MB
__device__ float g_bnsum[128], g_bnsumsq[128], g_bnscale[128], g_bnshift[128];

// ---------------- kernel 0: zero counters ----------------
__global__ void zero_kernel() {
    unsigned i = blockIdx.x * blockDim.x + threadIdx.x;
    if (i < NN) g_count[i] = 0;
    if (i < 128) { g_bnsum[i] = 0.f; g_bnsumsq[i] = 0.f; }
}

// ---------------- kernel 1: histogram of dst ----------------
__global__ void hist_kernel(const int* __restrict__ dst) {
    unsigned e = blockIdx.x * blockDim.x + threadIdx.x;
    if (e < EE) atomicAdd(&g_count[__ldg(dst + e)], 1);
}

// ---------------- kernel 2a: per-block inclusive scan (1024/block) ----------------
__global__ void scan1_kernel() {
    __shared__ int s[1024];
    int t = threadIdx.x;
    int i = blockIdx.x * 1024 + t;
    int c = (i < NN) ? g_count[i] : 0;
    s[t] = c;
    __syncthreads();
#pragma unroll
    for (int d = 1; d < 1024; d <<= 1) {
        int v = (t >= d) ? s[t - d] : 0;
        __syncthreads();
        s[t] += v;
        __syncthreads();
    }
    if (i < NN) g_incl[i] = s[t];
    if (t == 1023) g_bsum[blockIdx.x] = s[1023];
}

// ---------------- kernel 2b: exclusive scan of block sums (1 block, 128 thr) ----------------
__global__ void scan2_kernel(int nblocks) {
    __shared__ int s[128];
    int t = threadIdx.x;
    s[t] = (t < nblocks) ? g_bsum[t] : 0;
    __syncthreads();
#pragma unroll
    for (int d = 1; d < 128; d <<= 1) {
        int v = (t >= d) ? s[t - d] : 0;
        __syncthreads();
        s[t] += v;
        __syncthreads();
    }
    // exclusive: shift right by one
    g_boff[t] = (t == 0) ? 0 : s[t - 1];
}

// ---------------- kernel 2c: finalize offsets + cursors ----------------
__global__ void scan3_kernel() {
    unsigned i = blockIdx.x * blockDim.x + threadIdx.x;
    if (i >= NN) return;
    int incl = g_incl[i] + g_boff[i >> 10];
    g_offset[i + 1] = incl;
    g_cursor[i] = incl - g_count[i];
    if (i == 0) g_offset[0] = 0;
}

// ---------------- kernel 3: scatter edges into CSR order ----------------
__global__ void scatter_kernel(const int* __restrict__ src, const int* __restrict__ dst) {
    unsigned e = blockIdx.x * blockDim.x + threadIdx.x;
    if (e >= EE) return;
    int d = __ldg(dst + e);
    int pos = atomicAdd(&g_cursor[d], 1);
    g_ssrc[pos] = __ldg(src + e);
}

// ---------------- kernel 4: gather-aggregate (warp per node) + residual ----------------
__global__ void __launch_bounds__(256) agg_kernel(const float2* __restrict__ x2) {
    int gw = (blockIdx.x * 256 + threadIdx.x) >> 5;   // node id (uniform per warp)
    int lane = threadIdx.x & 31;
    if (gw >= NN) return;
    int beg = g_offset[gw], end = g_offset[gw + 1];
    float d0 = 0.f, d1 = 0.f, s0 = 0.f, s1 = 0.f;
    for (int base = beg; base < end; base += 32) {
        int m = end - base; if (m > 32) m = 32;
        int sl = (lane < m) ? __ldg(g_ssrc + base + lane) : 0;
#pragma unroll 4
        for (int i = 0; i < m; i++) {
            int s = __shfl_sync(0xFFFFFFFFu, sl, i);
            float2 v = __ldg(x2 + (size_t)s * 32 + lane);
            float m0 = fmaxf(v.x, 0.f) + EPSM;
            float m1 = fmaxf(v.y, 0.f) + EPSM;
            float e0 = __expf(m0), e1 = __expf(m1);
            d0 += e0; d1 += e1;
            s0 = fmaf(m0, e0, s0); s1 = fmaf(m1, e1, s1);
        }
    }
    float2 self = __ldg(x2 + (size_t)gw * 32 + lane);
    float2 r;
    r.x = s0 / (d0 + 1e-16f) + self.x;
    r.y = s1 / (d1 + 1e-16f) + self.y;
    reinterpret_cast<float2*>(g_aggout)[(size_t)gw * 32 + lane] = r;
}

// ---------------- kernel 5: Linear1 + BN partial stats ----------------
// 64 nodes/block, 256 threads, thread tile = 8 nodes x 4 cols. FMA-bound.
__global__ void __launch_bounds__(256) nodeA_kernel(const float* __restrict__ W1,
                                                    const float* __restrict__ b1) {
    __shared__ float s_in[64 * 64];    // [n][k] 16 KB
    __shared__ float s_W1[64 * 128];   // [k][c] 32 KB
    int t = threadIdx.x;
    int nb = blockIdx.x * 64;

    for (int i = t; i < 64 * 128; i += 256) s_W1[i] = __ldg(W1 + i);
    for (int i = t; i < 64 * 64; i += 256) {
        int n = i >> 6;
        s_in[i] = (nb + n < NN) ? g_aggout[(size_t)(nb + n) * 64 + (i & 63)] : 0.f;
    }
    __syncthreads();

    int c0 = (t & 31) * 4;
    int n0 = (t >> 5) * 8;
    float acc[8][4];
    float b0 = __ldg(&b1[c0]), bb1 = __ldg(&b1[c0 + 1]), b2v = __ldg(&b1[c0 + 2]), b3 = __ldg(&b1[c0 + 3]);
#pragma unroll
    for (int i = 0; i < 8; i++) { acc[i][0] = b0; acc[i][1] = bb1; acc[i][2] = b2v; acc[i][3] = b3; }

#pragma unroll 4
    for (int k = 0; k < 64; k++) {
        float4 w = *reinterpret_cast<const float4*>(&s_W1[k * 128 + c0]);
#pragma unroll
        for (int i = 0; i < 8; i++) {
            float a = s_in[(n0 + i) * 64 + k];
            acc[i][0] = fmaf(a, w.x, acc[i][0]);
            acc[i][1] = fmaf(a, w.y, acc[i][1]);
            acc[i][2] = fmaf(a, w.z, acc[i][2]);
            acc[i][3] = fmaf(a, w.w, acc[i][3]);
        }
    }

    float su[4] = {0.f, 0.f, 0.f, 0.f}, sq[4] = {0.f, 0.f, 0.f, 0.f};
#pragma unroll
    for (int i = 0; i < 8; i++) {
        int n = nb + n0 + i;
        if (n < NN) {
            *reinterpret_cast<float4*>(&g_h[(size_t)n * 128 + c0]) =
                make_float4(acc[i][0], acc[i][1], acc[i][2], acc[i][3]);
#pragma unroll
            for (int j = 0; j < 4; j++) { su[j] += acc[i][j]; sq[j] = fmaf(acc[i][j], acc[i][j], sq[j]); }
        }
    }
#pragma unroll
    for (int j = 0; j < 4; j++) {
        atomicAdd(&g_bnsum[c0 + j], su[j]);
        atomicAdd(&g_bnsumsq[c0 + j], sq[j]);
    }
}

// ---------------- kernel 6: BN finalize ----------------
__global__ void bnfin_kernel(const float* __restrict__ gam, const float* __restrict__ bet) {
    int c = threadIdx.x;
    float mean = g_bnsum[c] * (1.f / (float)NN);
    float var = g_bnsumsq[c] * (1.f / (float)NN) - mean * mean;
    float sc = __ldg(gam + c) * rsqrtf(var + 1e-5f);
    g_bnscale[c] = sc;
    g_bnshift[c] = __ldg(bet + c) - mean * sc;
}

// ---------------- kernel 7: BN+ReLU + Linear2 + LayerNorm + ReLU ----------------
// 32 nodes/block, 256 threads, thread tile = 2 nodes x 4 cols.
__global__ void __launch_bounds__(256) nodeB_kernel(const float* __restrict__ W2,
                                                    const float* __restrict__ b2,
                                                    const float* __restrict__ lng,
                                                    const float* __restrict__ lnb,
                                                    float* __restrict__ out) {
    __shared__ float s_W2[128 * 64];   // [k][c] 32 KB
    __shared__ float s_a[32 * 128];    // [n][k] 16 KB (reused as s_y after matmul)
    int t = threadIdx.x;
    int nb = blockIdx.x * 32;

    for (int i = t; i < 128 * 64; i += 256) s_W2[i] = __ldg(W2 + i);
    for (int i = t; i < 32 * 128; i += 256) {
        int n = i >> 7, k = i & 127;
        float v = g_h[(size_t)(nb + n) * 128 + k];
        v = fmaf(v, g_bnscale[k], g_bnshift[k]);
        s_a[i] = fmaxf(v, 0.f);
    }
    __syncthreads();

    int c0 = (t & 15) * 4;
    int n0 = (t >> 4) * 2;
    float acc[2][4];
    float b0 = __ldg(&b2[c0]), bb1 = __ldg(&b2[c0 + 1]), b2v = __ldg(&b2[c0 + 2]), b3 = __ldg(&b2[c0 + 3]);
    acc[0][0] = b0; acc[0][1] = bb1; acc[0][2] = b2v; acc[0][3] = b3;
    acc[1][0] = b0; acc[1][1] = bb1; acc[1][2] = b2v; acc[1][3] = b3;

#pragma unroll 4
    for (int k = 0; k < 128; k++) {
        float4 w = *reinterpret_cast<const float4*>(&s_W2[k * 64 + c0]);
        float a0 = s_a[n0 * 128 + k];
        float a1 = s_a[(n0 + 1) * 128 + k];
        acc[0][0] = fmaf(a0, w.x, acc[0][0]);
        acc[0][1] = fmaf(a0, w.y, acc[0][1]);
        acc[0][2] = fmaf(a0, w.z, acc[0][2]);
        acc[0][3] = fmaf(a0, w.w, acc[0][3]);
        acc[1][0] = fmaf(a1, w.x, acc[1][0]);
        acc[1][1] = fmaf(a1, w.y, acc[1][1]);
        acc[1][2] = fmaf(a1, w.z, acc[1][2]);
        acc[1][3] = fmaf(a1, w.w, acc[1][3]);
    }
    __syncthreads();   // everyone done reading s_a

    float* s_y = s_a;  // reuse: [n][64]
#pragma unroll
    for (int i = 0; i < 2; i++)
        *reinterpret_cast<float4*>(&s_y[(n0 + i) * 64 + c0]) =
            make_float4(acc[i][0], acc[i][1], acc[i][2], acc[i][3]);
    __syncthreads();

    // LayerNorm + ReLU: warp w handles nodes 4w..4w+3
    int w = t >> 5, lane = t & 31;
#pragma unroll
    for (int nn = 0; nn < 4; nn++) {
        int n = w * 4 + nn;
        float v0 = s_y[n * 64 + lane];
        float v1 = s_y[n * 64 + lane + 32];
        float sum = v0 + v1;
        float sq = v0 * v0 + v1 * v1;
#pragma unroll
        for (int o = 16; o > 0; o >>= 1) {
            sum += __shfl_xor_sync(0xFFFFFFFFu, sum, o);
            sq  += __shfl_xor_sync(0xFFFFFFFFu, sq, o);
        }
        float mean = sum * (1.f / 64.f);
        float var = sq * (1.f / 64.f) - mean * mean;
        float inv = rsqrtf(var + 1e-5f);
        size_t g = (size_t)(nb + n) * 64;
        float y0 = (v0 - mean) * inv * __ldg(lng + lane) + __ldg(lnb + lane);
        float y1 = (v1 - mean) * inv * __ldg(lng + lane + 32) + __ldg(lnb + lane + 32);
        out[g + lane] = fmaxf(y0, 0.f);
        out[g + lane + 32] = fmaxf(y1, 0.f);
    }
}

// ---------------- launcher ----------------
extern "C" void kernel_launch(void* const* d_in, const int* in_sizes, int n_in,
                              void* d_out, int out_size) {
    const float* x   = (const float*)d_in[0];
    const int*   ei  = (const int*)d_in[1];
    const float* W1  = (const float*)d_in[2];
    const float* b1  = (const float*)d_in[3];
    const float* bng = (const float*)d_in[4];
    const float* bnb = (const float*)d_in[5];
    const float* W2  = (const float*)d_in[6];
    const float* b2  = (const float*)d_in[7];
    const float* lng = (const float*)d_in[8];
    const float* lnb = (const float*)d_in[9];
    float* out = (float*)d_out;

    const int* src = ei;
    const int* dst = ei + EE;

    const int nscan = (NN + 1023) / 1024;   // 98

    zero_kernel<<<(NN + 255) / 256, 256>>>();
    hist_kernel<<<(EE + 255) / 256, 256>>>(dst);
    scan1_kernel<<<nscan, 1024>>>();
    scan2_kernel<<<1, 128>>>(nscan);
    scan3_kernel<<<(NN + 255) / 256, 256>>>();
    scatter_kernel<<<(EE + 255) / 256, 256>>>(src, dst);
    agg_kernel<<<(NN * 32 + 255) / 256, 256>>>((const float2*)x);
    nodeA_kernel<<<(NN + 63) / 64, 256>>>(W1, b1);
    bnfin_kernel<<<1, 128>>>(bng, bnb);
    nodeB_kernel<<<(NN + 31) / 32, 256>>>(W2, b2, lng, lnb, out);
}